// round 15
// baseline (speedup 1.0000x reference)
#include <cuda_runtime.h>

// ISTSimulator: B=65536, V=2, L=200 per-lane recurrence.
// Round 15: time-split. Pass A: state-only walk of steps 0-99, checkpoint
// (u,F) to __device__ scratch. Pass B: 2x blocks (seg 0: steps 0-99 from init;
// seg 1: steps 100-199 from checkpoint) -> 8192 resident warps on the R13
// body. Also: per-step Newton on r dropped; r reseeded via rcp every 8 steps.

#define LOG2E_F 1.4426950408889634f
#define SW 33                          // smem row stride (odd -> conflict-free)
#define BT 128                         // threads per block
#define MAXL 131072                    // scratch capacity (lanes)

__device__ float2 g_ckpt[MAXL];        // 1 MB checkpoint scratch

__device__ __forceinline__ float ex2a(float x) {
    float r; asm("ex2.approx.ftz.f32 %0, %1;" : "=f"(r) : "f"(x)); return r;
}
__device__ __forceinline__ float lg2a(float x) {
    float r; asm("lg2.approx.f32 %0, %1;" : "=f"(r) : "f"(x)); return r;
}
__device__ __forceinline__ float rcpa(float x) {
    float r; asm("rcp.approx.ftz.f32 %0, %1;" : "=f"(r) : "f"(x)); return r;
}

struct LS {
    float u, F;
    float lam, nlam, beta, nbeta, c2;
    float kd, nkd, kf, mu;
    float na, z0, c;
};

__device__ __forceinline__ void ls_init(LS& s, const float* p) {
    s.lam  = 0.001f * fmaxf(p[0], 0.0f);
    s.nlam = -s.lam;
    s.beta = fmaf(10.0f, fmaxf(p[1], 0.0f), 1.0f);
    s.nbeta = -s.beta;
    s.c2   = 0.5f * s.beta * (s.beta - 1.0f);
    s.kd   = p[2];
    s.nkd  = -s.kd;
    s.mu   = p[3];
    s.kf   = p[4];
    float a = LOG2E_F / p[6];
    s.z0 = p[5] * a;
    s.na = -a;
    s.c  = ex2a(s.na);
    s.u  = 1.0f;                       // u = 1 - D; stays in (0.38, 1]
    s.F  = 1e-12f;
}

// Process LEN steps starting at absolute step n0g. STORE: stage into sp[ofs..].
// cheap_all = warp-uniform (d_cheap && warp_geo).
template <int LEN, bool STORE>
__device__ __forceinline__ void grp(LS& s, bool cheap_all,
                                    float* sp, int ofs, int n0g)
{
    float zs = fmaf((float)n0g, s.na, s.z0);         // exact group-start z
    bool cheap = false;
    if (LEN >= 8) {
        float ze = fmaf((float)LEN, s.na, zs);
        // hazard: e pinned at reseed (inf/FTZ-0) while true g crosses back
        // within the group (z monotone -> predicate exact)
        bool pc = (zs >  126.0f && ze <  26.0f) ||
                  (zs < -126.0f && ze > -26.0f);
        cheap = cheap_all && !__any_sync(0xffffffffu, pc);
    }

    if (LEN >= 8 && cheap) {
        // exact reseed: d = lam*u^beta (MUFU, amortized /LEN)
        float l  = lg2a(s.u);
        float pw = ex2a(s.beta * l);
        float d  = s.lam * pw;
        float e  = ex2a(zs);
        #pragma unroll
        for (int h = 0; h < LEN / 8; ++h) {
            float r = rcpa(s.u);                     // r reseed per 8 steps
            #pragma unroll
            for (int jj = 0; jj < 8; ++jj) {
                float g = rcpa(1.0f + e);
                e *= s.c;
                float q = fmaf(s.mu, s.F, 1e-12f);
                s.F = __saturatef(fmaf(g, q, s.F));  // FFMA.SAT
                float x  = d * r;
                s.u -= d;
                float tt = fmaf(s.c2, x, s.nbeta);
                d *= fmaf(tt, x, 1.0f);              // d *= (1 - b*x + c2*x^2)
                if (STORE)
                    sp[ofs + h * 8 + jj] =
                        fmaf(s.kf, s.F, fmaf(s.nkd, s.u, s.kd));
            }
        }
    } else {
        // exact path: per-step lg2/ex2 pow + saturating ex2 sigmoid
        #pragma unroll
        for (int jj = 0; jj < LEN; ++jj) {
            float l  = lg2a(s.u);
            float pw = ex2a(s.beta * l);
            s.u = fmaf(s.nlam, pw, s.u);
            float z = fmaf((float)jj, s.na, zs);
            float e = ex2a(z);                       // saturates safely
            float g = rcpa(1.0f + e);
            float q = fmaf(s.mu, s.F, 1e-12f);
            s.F = __saturatef(fmaf(g, q, s.F));
            if (STORE)
                sp[ofs + jj] = fmaf(s.kf, s.F, fmaf(s.nkd, s.u, s.kd));
        }
    }
}

// Pass A: walk steps 0..99 state-only, checkpoint (u,F).
__global__ void __launch_bounds__(BT) ist_ckpt_kernel(const float* __restrict__ in)
{
    int lane = blockIdx.x * BT + threadIdx.x;
    LS s;
    ls_init(s, in + (size_t)lane * 7);
    bool cheap_all = __all_sync(0xffffffffu,
        (s.beta * s.lam < 0.05f) && (fabsf(s.na) < 126.0f));

    #pragma unroll 1
    for (int gidx = 0; gidx < 6; ++gidx)
        grp<16, false>(s, cheap_all, nullptr, 0, gidx * 16);
    grp<4, false>(s, cheap_all, nullptr, 0, 96);

    g_ckpt[lane] = make_float2(s.u, s.F);
}

// Pass B: two segments of 100 steps; seg 1 restores from checkpoint.
__global__ void __launch_bounds__(BT) ist_main_kernel(
    const float* __restrict__ in, float* __restrict__ out)
{
    __shared__ float sm[BT * SW];      // 16.9 KB
    int t = threadIdx.x;
    int seg = blockIdx.x & 1;
    int base_lane = (blockIdx.x >> 1) * BT;
    int lane = base_lane + t;

    LS s;
    ls_init(s, in + (size_t)lane * 7);
    bool cheap_all = __all_sync(0xffffffffu,
        (s.beta * s.lam < 0.05f) && (fabsf(s.na) < 126.0f));

    int n_base = seg * 100;
    if (seg) {
        float2 ck = g_ckpt[lane];
        s.u = ck.x;
        s.F = ck.y;
    }

    float* sp = &sm[t * SW];

    #pragma unroll 1
    for (int chunk = 0; chunk < 4; ++chunk) {
        int n0 = chunk * 32;                         // local to segment
        bool full = (chunk < 3);                     // 100 = 3*32 + 4

        if (full) {
            grp<16, true>(s, cheap_all, sp, 0,  n_base + n0);
            grp<16, true>(s, cheap_all, sp, 16, n_base + n0 + 16);
        } else {
            grp<4, true>(s, cheap_all, sp, 0, n_base + n0);
        }
        __syncthreads();
        if (full) {
            // 128 rows x 32 cols = 1024 float4, 8 per thread (R13-proven)
            #pragma unroll
            for (int it = 0; it < 8; ++it) {
                int q4 = it * (BT * 4) + t * 4;
                int r  = q4 >> 5;
                int cc = q4 & 31;
                int sb = r * SW + cc;
                float4 v;
                v.x = sm[sb];
                v.y = sm[sb + 1];
                v.z = sm[sb + 2];
                v.w = sm[sb + 3];
                *reinterpret_cast<float4*>(
                    &out[(size_t)(base_lane + r) * 200 + n_base + n0 + cc]) = v;
            }
        } else {
            // 128 rows x 4 cols: one float4 per thread (2% of traffic)
            int sb = t * SW;
            float4 v;
            v.x = sm[sb];
            v.y = sm[sb + 1];
            v.z = sm[sb + 2];
            v.w = sm[sb + 3];
            *reinterpret_cast<float4*>(
                &out[(size_t)(base_lane + t) * 200 + n_base + n0]) = v;
        }
        __syncthreads();
    }
}

// generic fallback for unexpected shapes
__global__ void __launch_bounds__(256) ist_generic(
    const float* __restrict__ in, float* __restrict__ out, int n_lanes)
{
    int tid = blockIdx.x * blockDim.x + threadIdx.x;
    if (tid >= n_lanes) return;
    const float* p = in + (size_t)tid * 7;
    float lam  = 0.001f * fmaxf(p[0], 0.0f);
    float beta = fmaf(10.0f, fmaxf(p[1], 0.0f), 1.0f);
    float kd = p[2], mu = p[3], kf = p[4];
    float a = LOG2E_F / p[6], z0 = p[5] * a;
    float u = 1.0f, F = 1e-12f, nf = 0.0f;
    float* o = out + (size_t)tid * 200;
    for (int n = 0; n < 200; ++n) {
        float l  = lg2a(fmaxf(u, 1e-12f));
        float pw = ex2a(beta * l);
        u = fminf(fmaxf(fmaf(-lam, pw, u), 0.0f), 1.0f);
        float z = fmaf(-nf, a, z0);
        float g = rcpa(1.0f + ex2a(z));
        float q = fmaf(mu, F, 1e-12f);
        F = __saturatef(fmaf(g, q, F));
        o[n] = fmaf(kf, F, fmaf(-kd, u, kd));
        nf += 1.0f;
    }
}

extern "C" void kernel_launch(void* const* d_in, const int* in_sizes, int n_in,
                              void* d_out, int out_size)
{
    const float* in = (const float*)d_in[0];
    float* out = (float*)d_out;
    int n_lanes = in_sizes[0] / 7;
    if (n_lanes % BT == 0 && n_lanes <= MAXL) {
        int nb = n_lanes / BT;
        ist_ckpt_kernel<<<nb, BT>>>(in);
        ist_main_kernel<<<2 * nb, BT>>>(in, out);
    } else {
        ist_generic<<<(n_lanes + 255) / 256, 256>>>(in, out, n_lanes);
    }
}

// round 16
// speedup vs baseline: 1.5094x; 1.5094x over previous
#include <cuda_runtime.h>

// ISTSimulator: B=65536, V=2, L=200 per-lane recurrence.
// Round 16: R13 structure + (a) float4 XOR-swizzled smem staging (STS.128 /
// LDS.128 / STG.128, conflict-free per phase) and (b) Newton-free r with rcp
// reseed per 8 steps (validated R15, rel_err ~1e-5). Taylor-propagated D +
// geometric sigmoid F, 16-step exact MUFU reseeds, warp-uniform hazard votes,
// FFMA.SAT clamp. 1024 blocks x 128 threads.

#define LOG2E_F 1.4426950408889634f
#define BT 128                         // threads per block

__device__ __forceinline__ float ex2a(float x) {
    float r; asm("ex2.approx.ftz.f32 %0, %1;" : "=f"(r) : "f"(x)); return r;
}
__device__ __forceinline__ float lg2a(float x) {
    float r; asm("lg2.approx.f32 %0, %1;" : "=f"(r) : "f"(x)); return r;
}
__device__ __forceinline__ float rcpa(float x) {
    float r; asm("rcp.approx.ftz.f32 %0, %1;" : "=f"(r) : "f"(x)); return r;
}

struct LS {
    float u, F;
    float lam, nlam, beta, nbeta, c2;
    float kd, nkd, kf, mu;
    float na, z0, c;
};

__device__ __forceinline__ void ls_init(LS& s, const float* p) {
    s.lam  = 0.001f * fmaxf(p[0], 0.0f);
    s.nlam = -s.lam;
    s.beta = fmaf(10.0f, fmaxf(p[1], 0.0f), 1.0f);
    s.nbeta = -s.beta;
    s.c2   = 0.5f * s.beta * (s.beta - 1.0f);
    s.kd   = p[2];
    s.nkd  = -s.kd;
    s.mu   = p[3];
    s.kf   = p[4];
    float a = LOG2E_F / p[6];
    s.z0 = p[5] * a;
    s.na = -a;
    s.c  = ex2a(s.na);
    s.u  = 1.0f;                       // u = 1 - D; stays in (0.38, 1]
    s.F  = 1e-12f;
}

// Process LEN steps (LEN in {8,16}) starting at absolute step n0g.
// Stage results as float4 into smrow[(ofs4 + k) ^ swz].
template <int LEN>
__device__ __forceinline__ void grp(LS& s, bool cheap_all, float4* smrow,
                                    int swz, int ofs4, int n0g)
{
    float zs = fmaf((float)n0g, s.na, s.z0);         // exact group-start z
    float ze = fmaf((float)LEN, s.na, zs);
    // hazard: e pinned at reseed (inf/FTZ-0) while true g crosses back within
    // the group (z monotone -> predicate exact). Benign saturation stays cheap.
    bool pc = (zs >  126.0f && ze <  26.0f) ||
              (zs < -126.0f && ze > -26.0f);
    bool cheap = cheap_all && !__any_sync(0xffffffffu, pc);

    float v0, v1, v2, v3;
    if (cheap) {
        // exact reseed: d = lam*u^beta (MUFU, amortized /LEN)
        float l  = lg2a(s.u);
        float pw = ex2a(s.beta * l);
        float d  = s.lam * pw;
        float e  = ex2a(zs);
        #pragma unroll
        for (int h = 0; h < LEN / 8; ++h) {
            float r = rcpa(s.u);                     // r reseed per 8 steps
            #pragma unroll
            for (int jj = 0; jj < 8; ++jj) {
                float g = rcpa(1.0f + e);
                e *= s.c;
                float q = fmaf(s.mu, s.F, 1e-12f);
                s.F = __saturatef(fmaf(g, q, s.F));  // FFMA.SAT
                float x  = d * r;
                s.u -= d;
                float tt = fmaf(s.c2, x, s.nbeta);
                d *= fmaf(tt, x, 1.0f);              // d *= (1 - b*x + c2*x^2)
                float val = fmaf(s.kf, s.F, fmaf(s.nkd, s.u, s.kd));
                if ((jj & 3) == 0) v0 = val;
                else if ((jj & 3) == 1) v1 = val;
                else if ((jj & 3) == 2) v2 = val;
                else {
                    v3 = val;
                    int j4 = ofs4 + ((h * 8 + jj) >> 2);
                    smrow[j4 ^ swz] = make_float4(v0, v1, v2, v3);
                }
            }
        }
    } else {
        // exact path: per-step lg2/ex2 pow + saturating ex2 sigmoid
        #pragma unroll
        for (int jj = 0; jj < LEN; ++jj) {
            float l  = lg2a(s.u);
            float pw = ex2a(s.beta * l);
            s.u = fmaf(s.nlam, pw, s.u);
            float z = fmaf((float)jj, s.na, zs);
            float e = ex2a(z);                       // saturates safely
            float g = rcpa(1.0f + e);
            float q = fmaf(s.mu, s.F, 1e-12f);
            s.F = __saturatef(fmaf(g, q, s.F));
            float val = fmaf(s.kf, s.F, fmaf(s.nkd, s.u, s.kd));
            if ((jj & 3) == 0) v0 = val;
            else if ((jj & 3) == 1) v1 = val;
            else if ((jj & 3) == 2) v2 = val;
            else {
                v3 = val;
                int j4 = ofs4 + (jj >> 2);
                smrow[j4 ^ swz] = make_float4(v0, v1, v2, v3);
            }
        }
    }
}

__global__ void __launch_bounds__(BT) ist_kernel(
    const float* __restrict__ in, float* __restrict__ out)
{
    __shared__ float4 sm4[BT * 8];     // 16 KB: 128 rows x 8 float4 (32 steps)
    int t = threadIdx.x;
    int base_lane = blockIdx.x * BT;

    LS s;
    ls_init(s, in + (size_t)(base_lane + t) * 7);
    bool cheap_all = __all_sync(0xffffffffu,
        (s.beta * s.lam < 0.05f) && (fabsf(s.na) < 126.0f));

    float4* smrow = &sm4[t * 8];
    const int swz = t & 7;             // XOR swizzle key (write side)

    // flush constants (full chunks): thread reads rows r = it*16 + r0,
    // fixed col group c4f. r&7 == r0&7 (16 = 0 mod 8) -> swizzle entry fixed.
    const int r0  = t >> 3;
    const int c4f = t & 7;
    const int rsw = c4f ^ (r0 & 7);

    #pragma unroll 1
    for (int chunk = 0; chunk < 7; ++chunk) {
        int n0 = chunk * 32;
        bool full = (chunk < 6);       // 200 = 6*32 + 8

        if (full) {
            grp<16>(s, cheap_all, smrow, swz, 0, n0);
            grp<16>(s, cheap_all, smrow, swz, 4, n0 + 16);
        } else {
            grp<8>(s, cheap_all, smrow, swz, 0, n0);
        }
        __syncthreads();

        if (full) {
            // 128 rows x 8 float4 = 1024 float4, 8 per thread.
            // LDS.128: phase lanes share r, distinct c4f -> conflict-free.
            // STG.128: 8 lanes per row -> 4 full 128B lines per warp.
            const float4* rp = &sm4[r0 * 8 + rsw];
            float* gp = out + (size_t)(base_lane + r0) * 200 + n0 + c4f * 4;
            #pragma unroll
            for (int it = 0; it < 8; ++it) {
                *reinterpret_cast<float4*>(gp) = *rp;
                rp += 16 * 8;          // +16 rows
                gp += 16 * 200;
            }
        } else {
            // 128 rows x 2 float4 = 256 float4, 2 per thread (4% of traffic)
            int rr  = t >> 1;
            int cc4 = t & 1;
            #pragma unroll
            for (int it = 0; it < 2; ++it) {
                int r = it * 64 + rr;
                float4 vv = sm4[r * 8 + (cc4 ^ (r & 7))];
                *reinterpret_cast<float4*>(
                    &out[(size_t)(base_lane + r) * 200 + n0 + cc4 * 4]) = vv;
            }
        }
        if (chunk < 6) __syncthreads();
    }
}

// generic fallback for unexpected shapes
__global__ void __launch_bounds__(256) ist_generic(
    const float* __restrict__ in, float* __restrict__ out, int n_lanes)
{
    int tid = blockIdx.x * blockDim.x + threadIdx.x;
    if (tid >= n_lanes) return;
    const float* p = in + (size_t)tid * 7;
    float lam  = 0.001f * fmaxf(p[0], 0.0f);
    float beta = fmaf(10.0f, fmaxf(p[1], 0.0f), 1.0f);
    float kd = p[2], mu = p[3], kf = p[4];
    float a = LOG2E_F / p[6], z0 = p[5] * a;
    float u = 1.0f, F = 1e-12f, nf = 0.0f;
    float* o = out + (size_t)tid * 200;
    for (int n = 0; n < 200; ++n) {
        float l  = lg2a(fmaxf(u, 1e-12f));
        float pw = ex2a(beta * l);
        u = fminf(fmaxf(fmaf(-lam, pw, u), 0.0f), 1.0f);
        float z = fmaf(-nf, a, z0);
        float g = rcpa(1.0f + ex2a(z));
        float q = fmaf(mu, F, 1e-12f);
        F = __saturatef(fmaf(g, q, F));
        o[n] = fmaf(kf, F, fmaf(-kd, u, kd));
        nf += 1.0f;
    }
}

extern "C" void kernel_launch(void* const* d_in, const int* in_sizes, int n_in,
                              void* d_out, int out_size)
{
    const float* in = (const float*)d_in[0];
    float* out = (float*)d_out;
    int n_lanes = in_sizes[0] / 7;
    if (n_lanes % BT == 0) {
        ist_kernel<<<n_lanes / BT, BT>>>(in, out);
    } else {
        ist_generic<<<(n_lanes + 255) / 256, 256>>>(in, out, n_lanes);
    }
}